// round 9
// baseline (speedup 1.0000x reference)
#include <cuda_runtime.h>
#include <cstdint>

// ---------------------------------------------------------------------------
// EdgeScoringMLP via bf16 tensor cores + 3-pass Dekker split (hi*hi+hi*lo+lo*hi).
//   logit(e) = W3 . relu( relu(LN(e_in @ W1 + b1)) @ W2 + b2 ) + b3
//   e_in @ W1 = Pa[i] + Pb[j] + a0*W1[256,:] + a1*W1[257,:]   (P precomputed)
// R9: edge kernel = R6 (best measured). Precompute retiled to 64x128/CTA for
//     2 CTAs/SM (was 1) — it is latency-bound, not bandwidth-bound.
// ---------------------------------------------------------------------------

#define HD 128
#define PCOL 256
#define MAXN 100000
#define PW 68              // padded row stride (u32): (4g+tig)%32 all-distinct

__device__ float g_P[(size_t)MAXN * PCOL];

// ---- bf16 helpers ---------------------------------------------------------
static __device__ __forceinline__ uint32_t pack_bf16x2(float lo, float hi) {
    uint32_t d;
    asm("cvt.rn.bf16x2.f32 %0, %1, %2;" : "=r"(d) : "f"(hi), "f"(lo));
    return d;
}
static __device__ __forceinline__ void split_pair(float x0, float x1,
                                                  uint32_t& hi, uint32_t& lo) {
    hi = pack_bf16x2(x0, x1);
    float h0 = __uint_as_float(hi << 16);
    float h1 = __uint_as_float(hi & 0xFFFF0000u);
    lo = pack_bf16x2(x0 - h0, x1 - h1);
}
static __device__ __forceinline__ void mma_bf16(
    float& c0, float& c1, float& c2, float& c3,
    uint32_t a0, uint32_t a1, uint32_t a2, uint32_t a3,
    uint32_t b0, uint32_t b1)
{
    asm volatile(
        "mma.sync.aligned.m16n8k16.row.col.f32.bf16.bf16.f32 "
        "{%0,%1,%2,%3},{%4,%5,%6,%7},{%8,%9},{%0,%1,%2,%3};"
        : "+f"(c0), "+f"(c1), "+f"(c2), "+f"(c3)
        : "r"(a0), "r"(a1), "r"(a2), "r"(a3), "r"(b0), "r"(b1));
}

// ---------------------------------------------------------------------------
// Kernel 1: P = emb @ Wsel.  Wsel col o (within half): W1[c + half*128][o].
// R9 tiling: CTA 256 thr = 8 warps; tile = 64 nodes x 128 cols
// (blockIdx.y = half). Warp (mt 0..3, nh 0..1): 16 rows x 64 cols.
// smem ~105 KB -> 2 CTAs/SM, 16 warps/SM.
// ---------------------------------------------------------------------------
__global__ void __launch_bounds__(256, 2)
precompute_kernel(const float* __restrict__ emb,
                  const float* __restrict__ W1,
                  float* __restrict__ P,
                  int N)
{
    extern __shared__ uint32_t smu[];
    uint32_t* Whi = smu;                  // [128 cols][PW]
    uint32_t* Wlo = Whi + 128 * PW;
    uint32_t* Ahi = Wlo + 128 * PW;       // [64 rows][PW]
    uint32_t* Alo = Ahi + 64 * PW;

    int tid  = threadIdx.x;
    int half = blockIdx.y;
    int n0g  = blockIdx.x * 64;

    // stage + split W half: Whi/Wlo[o][kp] = split(W1[2kp+half*128][o], W1[2kp+1+...][o])
    for (int t = tid; t < 128 * 64; t += 256) {
        int o = t & 127, kp = t >> 7;
        float e0 = W1[(size_t)(2 * kp     + half * 128) * HD + o];
        float e1 = W1[(size_t)(2 * kp + 1 + half * 128) * HD + o];
        uint32_t hi, lo; split_pair(e0, e1, hi, lo);
        Whi[o * PW + kp] = hi; Wlo[o * PW + kp] = lo;
    }
    // stage + split A tile: Ahi/Alo[r][kp] from emb[n0g+r][2kp..2kp+1]
    for (int t = tid; t < 64 * 64; t += 256) {
        int r = t >> 6, kp = t & 63;
        int node = n0g + r; if (node >= N) node = N - 1;
        float2 v = *(const float2*)(emb + (size_t)node * HD + 2 * kp);
        uint32_t hi, lo; split_pair(v.x, v.y, hi, lo);
        Ahi[r * PW + kp] = hi; Alo[r * PW + kp] = lo;
    }
    __syncthreads();

    int wid = tid >> 5, lane = tid & 31;
    int g = lane >> 2, tig = lane & 3;
    int mt = wid >> 1, nh = wid & 1;
    int m0 = mt * 16;

    float C[8][4];
    #pragma unroll
    for (int nt = 0; nt < 8; nt++)
        #pragma unroll
        for (int q = 0; q < 4; q++) C[nt][q] = 0.f;

    #pragma unroll
    for (int kt = 0; kt < 8; kt++) {
        int kb = kt * 8 + tig;
        int r0 = m0 + g;
        uint32_t ah0 = Ahi[r0       * PW + kb];
        uint32_t ah1 = Ahi[(r0 + 8) * PW + kb];
        uint32_t ah2 = Ahi[r0       * PW + kb + 4];
        uint32_t ah3 = Ahi[(r0 + 8) * PW + kb + 4];
        uint32_t al0 = Alo[r0       * PW + kb];
        uint32_t al1 = Alo[(r0 + 8) * PW + kb];
        uint32_t al2 = Alo[r0       * PW + kb + 4];
        uint32_t al3 = Alo[(r0 + 8) * PW + kb + 4];
        #pragma unroll
        for (int nt = 0; nt < 8; nt++) {
            int nc = nh * 64 + nt * 8 + g;
            uint32_t bh0 = Whi[nc * PW + kb], bh1 = Whi[nc * PW + kb + 4];
            uint32_t bl0 = Wlo[nc * PW + kb], bl1 = Wlo[nc * PW + kb + 4];
            mma_bf16(C[nt][0], C[nt][1], C[nt][2], C[nt][3],
                     ah0, ah1, ah2, ah3, bh0, bh1);
            mma_bf16(C[nt][0], C[nt][1], C[nt][2], C[nt][3],
                     ah0, ah1, ah2, ah3, bl0, bl1);
            mma_bf16(C[nt][0], C[nt][1], C[nt][2], C[nt][3],
                     al0, al1, al2, al3, bh0, bh1);
        }
    }

    int r0 = n0g + m0 + g;
    int r1 = r0 + 8;
    #pragma unroll
    for (int nt = 0; nt < 8; nt++) {
        int col = half * 128 + nh * 64 + nt * 8 + 2 * tig;
        if (r0 < N) *(float2*)(P + (size_t)r0 * PCOL + col) = make_float2(C[nt][0], C[nt][1]);
        if (r1 < N) *(float2*)(P + (size_t)r1 * PCOL + col) = make_float2(C[nt][2], C[nt][3]);
    }
}

// ---------------------------------------------------------------------------
// Kernel 2: persistent fused edge pipeline (R6 verbatim — best measured).
// 16 edges per warp-chunk, 2 CTAs/SM, LN consts in regs, lane prefetch.
// ---------------------------------------------------------------------------
__global__ void __launch_bounds__(256, 2)
edge_kernel(const float* __restrict__ P,
            const int* __restrict__ eidx,        // [2][E] int32
            const float* __restrict__ attr,      // [E][2]
            const float* __restrict__ W1,        // rows 256,257
            const float* __restrict__ b1,
            const float* __restrict__ lng,
            const float* __restrict__ lnb,
            const float* __restrict__ W2,        // [128][64]
            const float* __restrict__ b2,
            const float* __restrict__ W3,
            const float* __restrict__ b3,
            float* __restrict__ out,
            int E)
{
    extern __shared__ uint32_t smu[];
    uint32_t* W2hi = smu;                      // [64][PW]
    uint32_t* W2lo = W2hi + 64 * PW;
    uint32_t* Xbase = W2lo + 64 * PW;          // 8 warps x (Xhi[16][PW], Xlo[16][PW])
    float* w3s = (float*)(Xbase + 8 * 2 * 16 * PW);   // 64
    float* b2s = w3s + 64;                             // 64
    float* b3s = b2s + 64;                             // 1

    int tid = threadIdx.x;

    for (int t = tid; t < 64 * 64; t += 256) {
        int kp = t >> 6, o = t & 63;
        float e0 = W2[(size_t)(2 * kp)     * 64 + o];
        float e1 = W2[(size_t)(2 * kp + 1) * 64 + o];
        uint32_t hi, lo; split_pair(e0, e1, hi, lo);
        W2hi[o * PW + kp] = hi; W2lo[o * PW + kp] = lo;
    }
    if (tid < 64) { w3s[tid] = W3[tid]; b2s[tid] = b2[tid]; }
    if (tid == 0) b3s[0] = b3[0];
    __syncthreads();

    int wid = tid >> 5, lane = tid & 31;
    int g = lane >> 2, tig = lane & 3;
    uint32_t* Xhi = Xbase + wid * 2 * 16 * PW;
    uint32_t* Xlo = Xhi + 16 * PW;
    int c0 = 4 * lane;
    const float inv_h = 1.0f / 128.0f;
    const float2* attr2 = (const float2*)attr;

    float4 w1a_r = *(const float4*)(W1 + 256 * HD + c0);
    float4 w1b_r = *(const float4*)(W1 + 257 * HD + c0);
    float4 b1_r  = *(const float4*)(b1 + c0);
    float4 g_r   = *(const float4*)(lng + c0);
    float4 be_r  = *(const float4*)(lnb + c0);
    float  b3v   = b3s[0];

    int nchunks = (E + 15) >> 4;
    int wg = blockIdx.x * 8 + wid;
    int wstride = gridDim.x * 8;

    for (int ch = wg; ch < nchunks; ch += wstride) {
        int e_base = ch << 4;

        int e_l = e_base + (lane & 15); if (e_l >= E) e_l = E - 1;
        int    i_l = eidx[e_l];
        int    j_l = eidx[(size_t)E + e_l];
        float2 a_l = attr2[e_l];

        #pragma unroll 4
        for (int ee = 0; ee < 16; ee++) {
            int   i  = __shfl_sync(0xffffffffu, i_l, ee);
            int   j  = __shfl_sync(0xffffffffu, j_l, ee);
            float ax = __shfl_sync(0xffffffffu, a_l.x, ee);
            float ay = __shfl_sync(0xffffffffu, a_l.y, ee);

            float4 pa = *(const float4*)(P + (size_t)i * PCOL + c0);
            float4 pb = *(const float4*)(P + (size_t)j * PCOL + 128 + c0);

            float h0 = pa.x + pb.x + ax * w1a_r.x + ay * w1b_r.x + b1_r.x;
            float h1 = pa.y + pb.y + ax * w1a_r.y + ay * w1b_r.y + b1_r.y;
            float h2 = pa.z + pb.z + ax * w1a_r.z + ay * w1b_r.z + b1_r.z;
            float h3 = pa.w + pb.w + ax * w1a_r.w + ay * w1b_r.w + b1_r.w;

            float s  = h0 + h1 + h2 + h3;
            float sq = h0 * h0 + h1 * h1 + h2 * h2 + h3 * h3;
            #pragma unroll
            for (int off = 16; off > 0; off >>= 1) {
                s  += __shfl_xor_sync(0xffffffffu, s,  off);
                sq += __shfl_xor_sync(0xffffffffu, sq, off);
            }
            float mean = s * inv_h;
            float var  = sq * inv_h - mean * mean;
            float rstd = rsqrtf(var + 1e-5f);

            float x0 = fmaxf((h0 - mean) * rstd * g_r.x + be_r.x, 0.f);
            float x1 = fmaxf((h1 - mean) * rstd * g_r.y + be_r.y, 0.f);
            float x2 = fmaxf((h2 - mean) * rstd * g_r.z + be_r.z, 0.f);
            float x3 = fmaxf((h3 - mean) * rstd * g_r.w + be_r.w, 0.f);

            uint32_t hA, lA, hB, lB;
            split_pair(x0, x1, hA, lA);
            split_pair(x2, x3, hB, lB);
            *(uint2*)(Xhi + ee * PW + 2 * lane) = make_uint2(hA, hB);
            *(uint2*)(Xlo + ee * PW + 2 * lane) = make_uint2(lA, lB);
        }
        __syncwarp();

        float C[8][4];
        #pragma unroll
        for (int nt = 0; nt < 8; nt++) {
            float bb0 = b2s[8 * nt + 2 * tig];
            float bb1 = b2s[8 * nt + 2 * tig + 1];
            C[nt][0] = bb0; C[nt][1] = bb1;
            C[nt][2] = bb0; C[nt][3] = bb1;
        }

        #pragma unroll
        for (int kt = 0; kt < 8; kt++) {
            int kb = kt * 8 + tig;
            uint32_t ah0 = Xhi[g       * PW + kb];
            uint32_t ah1 = Xhi[(g + 8) * PW + kb];
            uint32_t ah2 = Xhi[g       * PW + kb + 4];
            uint32_t ah3 = Xhi[(g + 8) * PW + kb + 4];
            uint32_t al0 = Xlo[g       * PW + kb];
            uint32_t al1 = Xlo[(g + 8) * PW + kb];
            uint32_t al2 = Xlo[g       * PW + kb + 4];
            uint32_t al3 = Xlo[(g + 8) * PW + kb + 4];
            #pragma unroll
            for (int nt = 0; nt < 8; nt++) {
                int nc = 8 * nt + g;
                uint32_t bh0 = W2hi[nc * PW + kb], bh1 = W2hi[nc * PW + kb + 4];
                uint32_t bl0 = W2lo[nc * PW + kb], bl1 = W2lo[nc * PW + kb + 4];
                mma_bf16(C[nt][0], C[nt][1], C[nt][2], C[nt][3],
                         ah0, ah1, ah2, ah3, bh0, bh1);
                mma_bf16(C[nt][0], C[nt][1], C[nt][2], C[nt][3],
                         ah0, ah1, ah2, ah3, bl0, bl1);
                mma_bf16(C[nt][0], C[nt][1], C[nt][2], C[nt][3],
                         al0, al1, al2, al3, bh0, bh1);
            }
        }
        __syncwarp();

        float p0 = 0.f, p1 = 0.f;
        #pragma unroll
        for (int nt = 0; nt < 8; nt++) {
            float w30 = w3s[8 * nt + 2 * tig];
            float w31 = w3s[8 * nt + 2 * tig + 1];
            p0 += fmaxf(C[nt][0], 0.f) * w30 + fmaxf(C[nt][1], 0.f) * w31;
            p1 += fmaxf(C[nt][2], 0.f) * w30 + fmaxf(C[nt][3], 0.f) * w31;
        }
        p0 += __shfl_xor_sync(0xffffffffu, p0, 1);
        p0 += __shfl_xor_sync(0xffffffffu, p0, 2);
        p1 += __shfl_xor_sync(0xffffffffu, p1, 1);
        p1 += __shfl_xor_sync(0xffffffffu, p1, 2);

        if (tig == 0) {
            int er0 = e_base + g;
            int er1 = er0 + 8;
            if (er0 < E) out[er0] = p0 + b3v;
            if (er1 < E) out[er1] = p1 + b3v;
        }
    }
}

// ---------------------------------------------------------------------------
// Launch
// ---------------------------------------------------------------------------
extern "C" void kernel_launch(void* const* d_in, const int* in_sizes, int n_in,
                              void* d_out, int out_size)
{
    const float* node_embed = (const float*)d_in[0];
    const int*   eidx       = (const int*)d_in[1];
    const float* attr       = (const float*)d_in[2];
    const float* W1         = (const float*)d_in[3];
    const float* b1         = (const float*)d_in[4];
    const float* lng        = (const float*)d_in[5];
    const float* lnb        = (const float*)d_in[6];
    const float* W2         = (const float*)d_in[7];
    const float* b2         = (const float*)d_in[8];
    const float* W3         = (const float*)d_in[9];
    const float* b3         = (const float*)d_in[10];
    float* out = (float*)d_out;

    int N = in_sizes[0] / HD;
    int E = in_sizes[2] / 2;

    float* P = nullptr;
    cudaGetSymbolAddress((void**)&P, g_P);

    const int PRE_SMEM  = (2 * 128 * PW + 2 * 64 * PW) * 4;              // 104448 B
    const int EDGE_SMEM = (2 * 64 * PW + 8 * 2 * 16 * PW + 129) * 4;     // 104964 B

    cudaFuncSetAttribute(precompute_kernel,
                         cudaFuncAttributeMaxDynamicSharedMemorySize, PRE_SMEM);
    cudaFuncSetAttribute(edge_kernel,
                         cudaFuncAttributeMaxDynamicSharedMemorySize, EDGE_SMEM);

    dim3 pre_grid((N + 63) / 64, 2);
    precompute_kernel<<<pre_grid, 256, PRE_SMEM>>>(node_embed, W1, P, N);

    edge_kernel<<<296, 256, EDGE_SMEM>>>(P, eidx, attr, W1, b1, lng, lnb,
                                         W2, b2, W3, b3, out, E);
}

// round 12
// speedup vs baseline: 1.0387x; 1.0387x over previous
#include <cuda_runtime.h>
#include <cstdint>

// ---------------------------------------------------------------------------
// EdgeScoringMLP via bf16 tensor cores + 3-pass Dekker split (hi*hi+hi*lo+lo*hi).
//   logit(e) = W3 . relu( relu(LN(e_in @ W1 + b1)) @ W2 + b2 ) + b3
//   e_in @ W1 = Pa[i] + Pb[j] + a0*W1[256,:] + a1*W1[257,:]   (P precomputed)
// R12: warp-PAIR split edge kernel (wavefronts/edge 32 -> 28) with
//      DEADLOCK-PROOF sync: uniform trip counts + CTA-wide __syncthreads()
//      instead of named barriers (suspected hang source in R10/R11).
//      Precompute = R6 (proven 133us).
// ---------------------------------------------------------------------------

#define HD 128
#define PCOL 256
#define MAXN 100000
#define PW 68              // padded row stride (u32): (4g+tig)%32 all-distinct

__device__ float g_P[(size_t)MAXN * PCOL];

// ---- bf16 helpers ---------------------------------------------------------
static __device__ __forceinline__ uint32_t pack_bf16x2(float lo, float hi) {
    uint32_t d;
    asm("cvt.rn.bf16x2.f32 %0, %1, %2;" : "=r"(d) : "f"(hi), "f"(lo));
    return d;
}
static __device__ __forceinline__ void split_pair(float x0, float x1,
                                                  uint32_t& hi, uint32_t& lo) {
    hi = pack_bf16x2(x0, x1);
    float h0 = __uint_as_float(hi << 16);
    float h1 = __uint_as_float(hi & 0xFFFF0000u);
    lo = pack_bf16x2(x0 - h0, x1 - h1);
}
static __device__ __forceinline__ void mma_bf16(
    float& c0, float& c1, float& c2, float& c3,
    uint32_t a0, uint32_t a1, uint32_t a2, uint32_t a3,
    uint32_t b0, uint32_t b1)
{
    asm volatile(
        "mma.sync.aligned.m16n8k16.row.col.f32.bf16.bf16.f32 "
        "{%0,%1,%2,%3},{%4,%5,%6,%7},{%8,%9},{%0,%1,%2,%3};"
        : "+f"(c0), "+f"(c1), "+f"(c2), "+f"(c3)
        : "r"(a0), "r"(a1), "r"(a2), "r"(a3), "r"(b0), "r"(b1));
}

// ---------------------------------------------------------------------------
// Kernel 1: P = emb @ Wsel.  (R6 version — best measured: 128-node tiles)
// CTA 256 thr = 8 warps, tile 128 nodes x 128 cols (blockIdx.y = half).
// Warp (mt 0..3, nh 0..1): 32 nodes x 64 cols, two 16-row tiles share B.
// ---------------------------------------------------------------------------
__global__ void __launch_bounds__(256, 1)
precompute_kernel(const float* __restrict__ emb,
                  const float* __restrict__ W1,
                  float* __restrict__ P,
                  int N)
{
    extern __shared__ uint32_t smu[];
    uint32_t* Whi = smu;                  // [128][PW]
    uint32_t* Wlo = Whi + 128 * PW;
    uint32_t* Ahi = Wlo + 128 * PW;       // [128][PW]
    uint32_t* Alo = Ahi + 128 * PW;

    int tid  = threadIdx.x;
    int half = blockIdx.y;
    int n0g  = blockIdx.x * 128;

    for (int t = tid; t < 128 * 64; t += 256) {
        int o = t & 127, kp = t >> 7;
        float e0 = W1[(size_t)(2 * kp     + half * 128) * HD + o];
        float e1 = W1[(size_t)(2 * kp + 1 + half * 128) * HD + o];
        uint32_t hi, lo; split_pair(e0, e1, hi, lo);
        Whi[o * PW + kp] = hi; Wlo[o * PW + kp] = lo;
    }
    for (int t = tid; t < 128 * 64; t += 256) {
        int r = t >> 6, kp = t & 63;
        int node = n0g + r; if (node >= N) node = N - 1;
        float2 v = *(const float2*)(emb + (size_t)node * HD + 2 * kp);
        uint32_t hi, lo; split_pair(v.x, v.y, hi, lo);
        Ahi[r * PW + kp] = hi; Alo[r * PW + kp] = lo;
    }
    __syncthreads();

    int wid = tid >> 5, lane = tid & 31;
    int g = lane >> 2, tig = lane & 3;
    int mt = wid >> 1, nh = wid & 1;
    int m0 = mt * 32;

    float C[2][8][4];
    #pragma unroll
    for (int tt = 0; tt < 2; tt++)
        #pragma unroll
        for (int nt = 0; nt < 8; nt++)
            #pragma unroll
            for (int q = 0; q < 4; q++) C[tt][nt][q] = 0.f;

    #pragma unroll
    for (int kt = 0; kt < 8; kt++) {
        int kb = kt * 8 + tig;
        uint32_t ah[2][4], al[2][4];
        #pragma unroll
        for (int tt = 0; tt < 2; tt++) {
            int r0 = m0 + tt * 16 + g;
            ah[tt][0] = Ahi[r0       * PW + kb];
            ah[tt][1] = Ahi[(r0 + 8) * PW + kb];
            ah[tt][2] = Ahi[r0       * PW + kb + 4];
            ah[tt][3] = Ahi[(r0 + 8) * PW + kb + 4];
            al[tt][0] = Alo[r0       * PW + kb];
            al[tt][1] = Alo[(r0 + 8) * PW + kb];
            al[tt][2] = Alo[r0       * PW + kb + 4];
            al[tt][3] = Alo[(r0 + 8) * PW + kb + 4];
        }
        #pragma unroll
        for (int nt = 0; nt < 8; nt++) {
            int nc = nh * 64 + nt * 8 + g;
            uint32_t bh0 = Whi[nc * PW + kb], bh1 = Whi[nc * PW + kb + 4];
            uint32_t bl0 = Wlo[nc * PW + kb], bl1 = Wlo[nc * PW + kb + 4];
            #pragma unroll
            for (int tt = 0; tt < 2; tt++) {
                mma_bf16(C[tt][nt][0], C[tt][nt][1], C[tt][nt][2], C[tt][nt][3],
                         ah[tt][0], ah[tt][1], ah[tt][2], ah[tt][3], bh0, bh1);
                mma_bf16(C[tt][nt][0], C[tt][nt][1], C[tt][nt][2], C[tt][nt][3],
                         ah[tt][0], ah[tt][1], ah[tt][2], ah[tt][3], bl0, bl1);
                mma_bf16(C[tt][nt][0], C[tt][nt][1], C[tt][nt][2], C[tt][nt][3],
                         al[tt][0], al[tt][1], al[tt][2], al[tt][3], bh0, bh1);
            }
        }
    }

    #pragma unroll
    for (int tt = 0; tt < 2; tt++) {
        int r0 = n0g + m0 + tt * 16 + g;
        int r1 = r0 + 8;
        #pragma unroll
        for (int nt = 0; nt < 8; nt++) {
            int col = half * 128 + nh * 64 + nt * 8 + 2 * tig;
            if (r0 < N) *(float2*)(P + (size_t)r0 * PCOL + col) =
                make_float2(C[tt][nt][0], C[tt][nt][1]);
            if (r1 < N) *(float2*)(P + (size_t)r1 * PCOL + col) =
                make_float2(C[tt][nt][2], C[tt][nt][3]);
        }
    }
}

// ---------------------------------------------------------------------------
// Kernel 2: persistent fused edge pipeline, warp-PAIR split, lockstep sync.
// CTA 256 thr = 4 pairs. Iteration it: pair pr handles chunk
// (it*gridDim.x + blockIdx.x)*4 + pr (32 edges). ALL warps run the same
// niter and hit the same __syncthreads() — no divergent barriers possible.
// Warp wp of a pair gathers rows [16wp,16wp+16), then computes all 32 rows
// x its own 32 output columns; partial W3-dots combined through smem.
// ---------------------------------------------------------------------------
__global__ void __launch_bounds__(256, 2)
edge_kernel(const float* __restrict__ P,
            const int* __restrict__ eidx,        // [2][E] int32
            const float* __restrict__ attr,      // [E][2]
            const float* __restrict__ W1,        // rows 256,257
            const float* __restrict__ b1,
            const float* __restrict__ lng,
            const float* __restrict__ lnb,
            const float* __restrict__ W2,        // [128][64]
            const float* __restrict__ b2,
            const float* __restrict__ W3,
            const float* __restrict__ b3,
            float* __restrict__ out,
            int E)
{
    extern __shared__ uint32_t smu[];
    uint32_t* W2hi = smu;                      // [64][PW]
    uint32_t* W2lo = W2hi + 64 * PW;
    uint32_t* Xbase = W2lo + 64 * PW;          // 4 pairs x (Xhi[32][PW], Xlo[32][PW])
    float* ps  = (float*)(Xbase + 4 * 2 * 32 * PW);   // [4 pairs][32 rows][2]
    float* w3s = ps + 4 * 32 * 2;              // 64
    float* b2s = w3s + 64;                     // 64
    float* b3s = b2s + 64;                     // 1

    int tid = threadIdx.x;

    for (int t = tid; t < 64 * 64; t += 256) {
        int kp = t >> 6, o = t & 63;
        float e0 = W2[(size_t)(2 * kp)     * 64 + o];
        float e1 = W2[(size_t)(2 * kp + 1) * 64 + o];
        uint32_t hi, lo; split_pair(e0, e1, hi, lo);
        W2hi[o * PW + kp] = hi; W2lo[o * PW + kp] = lo;
    }
    if (tid < 64) { w3s[tid] = W3[tid]; b2s[tid] = b2[tid]; }
    if (tid == 0) b3s[0] = b3[0];
    __syncthreads();

    int wid = tid >> 5, lane = tid & 31;
    int g = lane >> 2, tig = lane & 3;
    int pr = wid >> 1;          // pair 0..3
    int wp = wid & 1;           // warp-in-pair
    uint32_t* Xhi = Xbase + pr * 2 * 32 * PW;
    uint32_t* Xlo = Xhi + 32 * PW;
    float* psp = ps + pr * 32 * 2;
    int c0 = 4 * lane;
    int colbase = 32 * wp;      // this warp's 32 output columns
    const float inv_h = 1.0f / 128.0f;
    const float2* attr2 = (const float2*)attr;

    // hoisted per-lane LN constants
    float4 w1a_r = *(const float4*)(W1 + 256 * HD + c0);
    float4 w1b_r = *(const float4*)(W1 + 257 * HD + c0);
    float4 b1_r  = *(const float4*)(b1 + c0);
    float4 g_r   = *(const float4*)(lng + c0);
    float4 be_r  = *(const float4*)(lnb + c0);
    float  b3v   = b3s[0];

    // uniform trip count for ALL warps in the CTA
    int nchunks = (E + 31) >> 5;                       // 32-edge chunks
    int chunks_per_iter = gridDim.x * 4;               // 4 pairs per CTA
    int niter = (nchunks + chunks_per_iter - 1) / chunks_per_iter;

    for (int it = 0; it < niter; it++) {
        int ch = (it * gridDim.x + blockIdx.x) * 4 + pr;   // may exceed nchunks
        long long e_base_ll = (long long)ch << 5;
        int e_base = (e_base_ll >= E) ? (E - 1) : (int)e_base_ll;  // clamp base for loads
        int e_base_real = (int)((e_base_ll < E) ? e_base_ll : -1); // -1 => no stores

        int my_base = e_base + 16 * wp;

        // lane-parallel prefetch of this warp's 16 edges (clamped)
        int e_l = my_base + (lane & 15); if (e_l >= E) e_l = E - 1;
        int    i_l = eidx[e_l];
        int    j_l = eidx[(size_t)E + e_l];
        float2 a_l = attr2[e_l];

        // ---- gather + LN + ReLU + split-pack -> X rows [16wp, 16wp+16) ----
        #pragma unroll 4
        for (int ee = 0; ee < 16; ee++) {
            int   i  = __shfl_sync(0xffffffffu, i_l, ee);
            int   j  = __shfl_sync(0xffffffffu, j_l, ee);
            float ax = __shfl_sync(0xffffffffu, a_l.x, ee);
            float ay = __shfl_sync(0xffffffffu, a_l.y, ee);

            float4 pa = *(const float4*)(P + (size_t)i * PCOL + c0);
            float4 pb = *(const float4*)(P + (size_t)j * PCOL + 128 + c0);

            float h0 = pa.x + pb.x + ax * w1a_r.x + ay * w1b_r.x + b1_r.x;
            float h1 = pa.y + pb.y + ax * w1a_r.y + ay * w1b_r.y + b1_r.y;
            float h2 = pa.z + pb.z + ax * w1a_r.z + ay * w1b_r.z + b1_r.z;
            float h3 = pa.w + pb.w + ax * w1a_r.w + ay * w1b_r.w + b1_r.w;

            float s  = h0 + h1 + h2 + h3;
            float sq = h0 * h0 + h1 * h1 + h2 * h2 + h3 * h3;
            #pragma unroll
            for (int off = 16; off > 0; off >>= 1) {
                s  += __shfl_xor_sync(0xffffffffu, s,  off);
                sq += __shfl_xor_sync(0xffffffffu, sq, off);
            }
            float mean = s * inv_h;
            float var  = sq * inv_h - mean * mean;
            float rstd = rsqrtf(var + 1e-5f);

            float x0 = fmaxf((h0 - mean) * rstd * g_r.x + be_r.x, 0.f);
            float x1 = fmaxf((h1 - mean) * rstd * g_r.y + be_r.y, 0.f);
            float x2 = fmaxf((h2 - mean) * rstd * g_r.z + be_r.z, 0.f);
            float x3 = fmaxf((h3 - mean) * rstd * g_r.w + be_r.w, 0.f);

            uint32_t hA, lA, hB, lB;
            split_pair(x0, x1, hA, lA);
            split_pair(x2, x3, hB, lB);
            int row = 16 * wp + ee;
            *(uint2*)(Xhi + row * PW + 2 * lane) = make_uint2(hA, hB);
            *(uint2*)(Xlo + row * PW + 2 * lane) = make_uint2(lA, lB);
        }
        __syncthreads();   // all pairs' X tiles complete (uniform)

        // ---- GEMM2: C[32 rows][32 cols owned by this warp] ----
        float C[2][4][4];
        #pragma unroll
        for (int nt = 0; nt < 4; nt++) {
            float bb0 = b2s[colbase + 8 * nt + 2 * tig];
            float bb1 = b2s[colbase + 8 * nt + 2 * tig + 1];
            #pragma unroll
            for (int mt = 0; mt < 2; mt++) {
                C[mt][nt][0] = bb0; C[mt][nt][1] = bb1;
                C[mt][nt][2] = bb0; C[mt][nt][3] = bb1;
            }
        }

        #pragma unroll
        for (int kt = 0; kt < 8; kt++) {
            int kb = kt * 8 + tig;
            // B fragments for this warp's 4 col-tiles (shared across mt)
            uint32_t B[4][4];
            #pragma unroll
            for (int nt = 0; nt < 4; nt++) {
                int nc = colbase + 8 * nt + g;
                B[nt][0] = W2hi[nc * PW + kb];
                B[nt][1] = W2hi[nc * PW + kb + 4];
                B[nt][2] = W2lo[nc * PW + kb];
                B[nt][3] = W2lo[nc * PW + kb + 4];
            }
            #pragma unroll
            for (int mt = 0; mt < 2; mt++) {
                int r0 = 16 * mt + g;
                uint32_t ah0 = Xhi[r0       * PW + kb];
                uint32_t ah1 = Xhi[(r0 + 8) * PW + kb];
                uint32_t ah2 = Xhi[r0       * PW + kb + 4];
                uint32_t ah3 = Xhi[(r0 + 8) * PW + kb + 4];
                uint32_t al0 = Xlo[r0       * PW + kb];
                uint32_t al1 = Xlo[(r0 + 8) * PW + kb];
                uint32_t al2 = Xlo[r0       * PW + kb + 4];
                uint32_t al3 = Xlo[(r0 + 8) * PW + kb + 4];
                #pragma unroll
                for (int nt = 0; nt < 4; nt++) {
                    mma_bf16(C[mt][nt][0], C[mt][nt][1], C[mt][nt][2], C[mt][nt][3],
                             ah0, ah1, ah2, ah3, B[nt][0], B[nt][1]);
                    mma_bf16(C[mt][nt][0], C[mt][nt][1], C[mt][nt][2], C[mt][nt][3],
                             ah0, ah1, ah2, ah3, B[nt][2], B[nt][3]);
                    mma_bf16(C[mt][nt][0], C[mt][nt][1], C[mt][nt][2], C[mt][nt][3],
                             al0, al1, al2, al3, B[nt][0], B[nt][1]);
                }
            }
        }

        // ---- ReLU + partial W3 dot over this warp's 32 cols ----
        #pragma unroll
        for (int mt = 0; mt < 2; mt++) {
            float p0 = 0.f, p1 = 0.f;
            #pragma unroll
            for (int nt = 0; nt < 4; nt++) {
                float w30 = w3s[colbase + 8 * nt + 2 * tig];
                float w31 = w3s[colbase + 8 * nt + 2 * tig + 1];
                p0 += fmaxf(C[mt][nt][0], 0.f) * w30 + fmaxf(C[mt][nt][1], 0.f) * w31;
                p1 += fmaxf(C[mt][nt][2], 0.f) * w30 + fmaxf(C[mt][nt][3], 0.f) * w31;
            }
            p0 += __shfl_xor_sync(0xffffffffu, p0, 1);
            p0 += __shfl_xor_sync(0xffffffffu, p0, 2);
            p1 += __shfl_xor_sync(0xffffffffu, p1, 1);
            p1 += __shfl_xor_sync(0xffffffffu, p1, 2);
            if (tig == 0) {
                psp[(16 * mt + g)     * 2 + wp] = p0;
                psp[(16 * mt + g + 8) * 2 + wp] = p1;
            }
        }
        __syncthreads();   // all partials ready (uniform)

        // ---- combine: warp wp writes edges [16wp, 16wp+16) ----
        if (lane < 16 && e_base_real >= 0) {
            int row = 16 * wp + lane;
            float v = psp[row * 2] + psp[row * 2 + 1];
            int e = e_base_real + row;
            if (e < E) out[e] = v + b3v;
        }
        __syncthreads();   // combine-reads done before next iter's psp writes
    }
}

// ---------------------------------------------------------------------------
// Launch
// ---------------------------------------------------------------------------
extern "C" void kernel_launch(void* const* d_in, const int* in_sizes, int n_in,
                              void* d_out, int out_size)
{
    const float* node_embed = (const float*)d_in[0];
    const int*   eidx       = (const int*)d_in[1];
    const float* attr       = (const float*)d_in[2];
    const float* W1         = (const float*)d_in[3];
    const float* b1         = (const float*)d_in[4];
    const float* lng        = (const float*)d_in[5];
    const float* lnb        = (const float*)d_in[6];
    const float* W2         = (const float*)d_in[7];
    const float* b2         = (const float*)d_in[8];
    const float* W3         = (const float*)d_in[9];
    const float* b3         = (const float*)d_in[10];
    float* out = (float*)d_out;

    int N = in_sizes[0] / HD;
    int E = in_sizes[2] / 2;

    float* P = nullptr;
    cudaGetSymbolAddress((void**)&P, g_P);

    const int PRE_SMEM  = 4 * 128 * PW * 4;                                    // 139264 B
    const int EDGE_SMEM = (2 * 64 * PW + 4 * 2 * 32 * PW + 4 * 32 * 2 + 129) * 4; // 105988 B

    cudaFuncSetAttribute(precompute_kernel,
                         cudaFuncAttributeMaxDynamicSharedMemorySize, PRE_SMEM);
    cudaFuncSetAttribute(edge_kernel,
                         cudaFuncAttributeMaxDynamicSharedMemorySize, EDGE_SMEM);

    dim3 pre_grid((N + 127) / 128, 2);
    precompute_kernel<<<pre_grid, 256, PRE_SMEM>>>(node_embed, W1, P, N);

    edge_kernel<<<296, 256, EDGE_SMEM>>>(P, eidx, attr, W1, b1, lng, lnb,
                                         W2, b2, W3, b3, out, E);
}

// round 14
// speedup vs baseline: 1.1667x; 1.1232x over previous
#include <cuda_runtime.h>
#include <cuda_fp16.h>
#include <cstdint>

// ---------------------------------------------------------------------------
// EdgeScoringMLP: logit(e) = W3 . relu( relu(LN(e_in @ W1 + b1)) @ W2 + b2 ) + b3
//   e_in @ W1 = Pa[i] + Pb[j] + a0*W1[256,:] + a1*W1[257,:]   (P precomputed)
// R14: tcgen05 unavailable (harness targets compute_100; 'a' features rejected).
//      Edge GEMM2 switched bf16-3pass -> fp16-2pass Dekker:
//        D = ahi*bhi + alo*bhi = a * fp16(b);  error ~2^-12 rel (~1e-4 final)
//      -> W2-lo array eliminated: B-fragment smem traffic halves (16->8
//      wf/edge), mma count 24->16/chunk. Everything else = R6 (best measured).
//      Precompute stays bf16-3pass (P error 4e-6, proven).
// ---------------------------------------------------------------------------

#define HD 128
#define PCOL 256
#define MAXN 100000
#define PW 68              // padded row stride (u32): (4g+tig)%32 all-distinct

__device__ float g_P[(size_t)MAXN * PCOL];

// ---- bf16 helpers (precompute kernel) -------------------------------------
static __device__ __forceinline__ uint32_t pack_bf16x2(float lo, float hi) {
    uint32_t d;
    asm("cvt.rn.bf16x2.f32 %0, %1, %2;" : "=r"(d) : "f"(hi), "f"(lo));
    return d;
}
static __device__ __forceinline__ void split_pair(float x0, float x1,
                                                  uint32_t& hi, uint32_t& lo) {
    hi = pack_bf16x2(x0, x1);
    float h0 = __uint_as_float(hi << 16);
    float h1 = __uint_as_float(hi & 0xFFFF0000u);
    lo = pack_bf16x2(x0 - h0, x1 - h1);
}
static __device__ __forceinline__ void mma_bf16(
    float& c0, float& c1, float& c2, float& c3,
    uint32_t a0, uint32_t a1, uint32_t a2, uint32_t a3,
    uint32_t b0, uint32_t b1)
{
    asm volatile(
        "mma.sync.aligned.m16n8k16.row.col.f32.bf16.bf16.f32 "
        "{%0,%1,%2,%3},{%4,%5,%6,%7},{%8,%9},{%0,%1,%2,%3};"
        : "+f"(c0), "+f"(c1), "+f"(c2), "+f"(c3)
        : "r"(a0), "r"(a1), "r"(a2), "r"(a3), "r"(b0), "r"(b1));
}

// ---- fp16 helpers (edge kernel) -------------------------------------------
static __device__ __forceinline__ uint32_t pack_f16x2(float x0, float x1) {
    uint32_t d;   // lower half = x0, upper half = x1
    asm("cvt.rn.f16x2.f32 %0, %1, %2;" : "=r"(d) : "f"(x1), "f"(x0));
    return d;
}
static __device__ __forceinline__ void split_pair_f16(float x0, float x1,
                                                      uint32_t& hi, uint32_t& lo) {
    hi = pack_f16x2(x0, x1);
    __half2 h2 = *reinterpret_cast<__half2*>(&hi);
    float2 f = __half22float2(h2);        // f.x = lower(x0hi), f.y = upper(x1hi)
    lo = pack_f16x2(x0 - f.x, x1 - f.y);
}
static __device__ __forceinline__ void mma_f16(
    float& c0, float& c1, float& c2, float& c3,
    uint32_t a0, uint32_t a1, uint32_t a2, uint32_t a3,
    uint32_t b0, uint32_t b1)
{
    asm volatile(
        "mma.sync.aligned.m16n8k16.row.col.f32.f16.f16.f32 "
        "{%0,%1,%2,%3},{%4,%5,%6,%7},{%8,%9},{%0,%1,%2,%3};"
        : "+f"(c0), "+f"(c1), "+f"(c2), "+f"(c3)
        : "r"(a0), "r"(a1), "r"(a2), "r"(a3), "r"(b0), "r"(b1));
}

// ---------------------------------------------------------------------------
// Kernel 1: P = emb @ Wsel.  (R6 version — best measured, bf16 3-pass)
// CTA 256 thr = 8 warps, tile 128 nodes x 128 cols (blockIdx.y = half).
// ---------------------------------------------------------------------------
__global__ void __launch_bounds__(256, 1)
precompute_kernel(const float* __restrict__ emb,
                  const float* __restrict__ W1,
                  float* __restrict__ P,
                  int N)
{
    extern __shared__ uint32_t smu[];
    uint32_t* Whi = smu;                  // [128][PW]
    uint32_t* Wlo = Whi + 128 * PW;
    uint32_t* Ahi = Wlo + 128 * PW;       // [128][PW]
    uint32_t* Alo = Ahi + 128 * PW;

    int tid  = threadIdx.x;
    int half = blockIdx.y;
    int n0g  = blockIdx.x * 128;

    for (int t = tid; t < 128 * 64; t += 256) {
        int o = t & 127, kp = t >> 7;
        float e0 = W1[(size_t)(2 * kp     + half * 128) * HD + o];
        float e1 = W1[(size_t)(2 * kp + 1 + half * 128) * HD + o];
        uint32_t hi, lo; split_pair(e0, e1, hi, lo);
        Whi[o * PW + kp] = hi; Wlo[o * PW + kp] = lo;
    }
    for (int t = tid; t < 128 * 64; t += 256) {
        int r = t >> 6, kp = t & 63;
        int node = n0g + r; if (node >= N) node = N - 1;
        float2 v = *(const float2*)(emb + (size_t)node * HD + 2 * kp);
        uint32_t hi, lo; split_pair(v.x, v.y, hi, lo);
        Ahi[r * PW + kp] = hi; Alo[r * PW + kp] = lo;
    }
    __syncthreads();

    int wid = tid >> 5, lane = tid & 31;
    int g = lane >> 2, tig = lane & 3;
    int mt = wid >> 1, nh = wid & 1;
    int m0 = mt * 32;

    float C[2][8][4];
    #pragma unroll
    for (int tt = 0; tt < 2; tt++)
        #pragma unroll
        for (int nt = 0; nt < 8; nt++)
            #pragma unroll
            for (int q = 0; q < 4; q++) C[tt][nt][q] = 0.f;

    #pragma unroll
    for (int kt = 0; kt < 8; kt++) {
        int kb = kt * 8 + tig;
        uint32_t ah[2][4], al[2][4];
        #pragma unroll
        for (int tt = 0; tt < 2; tt++) {
            int r0 = m0 + tt * 16 + g;
            ah[tt][0] = Ahi[r0       * PW + kb];
            ah[tt][1] = Ahi[(r0 + 8) * PW + kb];
            ah[tt][2] = Ahi[r0       * PW + kb + 4];
            ah[tt][3] = Ahi[(r0 + 8) * PW + kb + 4];
            al[tt][0] = Alo[r0       * PW + kb];
            al[tt][1] = Alo[(r0 + 8) * PW + kb];
            al[tt][2] = Alo[r0       * PW + kb + 4];
            al[tt][3] = Alo[(r0 + 8) * PW + kb + 4];
        }
        #pragma unroll
        for (int nt = 0; nt < 8; nt++) {
            int nc = nh * 64 + nt * 8 + g;
            uint32_t bh0 = Whi[nc * PW + kb], bh1 = Whi[nc * PW + kb + 4];
            uint32_t bl0 = Wlo[nc * PW + kb], bl1 = Wlo[nc * PW + kb + 4];
            #pragma unroll
            for (int tt = 0; tt < 2; tt++) {
                mma_bf16(C[tt][nt][0], C[tt][nt][1], C[tt][nt][2], C[tt][nt][3],
                         ah[tt][0], ah[tt][1], ah[tt][2], ah[tt][3], bh0, bh1);
                mma_bf16(C[tt][nt][0], C[tt][nt][1], C[tt][nt][2], C[tt][nt][3],
                         ah[tt][0], ah[tt][1], ah[tt][2], ah[tt][3], bl0, bl1);
                mma_bf16(C[tt][nt][0], C[tt][nt][1], C[tt][nt][2], C[tt][nt][3],
                         al[tt][0], al[tt][1], al[tt][2], al[tt][3], bh0, bh1);
            }
        }
    }

    #pragma unroll
    for (int tt = 0; tt < 2; tt++) {
        int r0 = n0g + m0 + tt * 16 + g;
        int r1 = r0 + 8;
        #pragma unroll
        for (int nt = 0; nt < 8; nt++) {
            int col = half * 128 + nh * 64 + nt * 8 + 2 * tig;
            if (r0 < N) *(float2*)(P + (size_t)r0 * PCOL + col) =
                make_float2(C[tt][nt][0], C[tt][nt][1]);
            if (r1 < N) *(float2*)(P + (size_t)r1 * PCOL + col) =
                make_float2(C[tt][nt][2], C[tt][nt][3]);
        }
    }
}

// ---------------------------------------------------------------------------
// Kernel 2: persistent fused edge pipeline (R6 structure, fp16 2-pass).
// 16 edges per warp-chunk, 2 CTAs/SM, LN consts in regs, lane prefetch.
// GEMM2: D = Xhi@W2h + Xlo@W2h  (W2h = fp16(W2); no lo array for B).
// ---------------------------------------------------------------------------
__global__ void __launch_bounds__(256, 2)
edge_kernel(const float* __restrict__ P,
            const int* __restrict__ eidx,        // [2][E] int32
            const float* __restrict__ attr,      // [E][2]
            const float* __restrict__ W1,        // rows 256,257
            const float* __restrict__ b1,
            const float* __restrict__ lng,
            const float* __restrict__ lnb,
            const float* __restrict__ W2,        // [128][64]
            const float* __restrict__ b2,
            const float* __restrict__ W3,
            const float* __restrict__ b3,
            float* __restrict__ out,
            int E)
{
    extern __shared__ uint32_t smu[];
    uint32_t* W2h  = smu;                      // [64][PW]   fp16x2 packed
    uint32_t* Xbase = W2h + 64 * PW;           // 8 warps x (Xhi[16][PW], Xlo[16][PW])
    float* w3s = (float*)(Xbase + 8 * 2 * 16 * PW);   // 64
    float* b2s = w3s + 64;                             // 64
    float* b3s = b2s + 64;                             // 1

    int tid = threadIdx.x;

    // stage W2 -> packed fp16x2 (hi only): W2h[o][kp] = f16(W2[2kp][o], W2[2kp+1][o])
    for (int t = tid; t < 64 * 64; t += 256) {
        int kp = t >> 6, o = t & 63;
        float e0 = W2[(size_t)(2 * kp)     * 64 + o];
        float e1 = W2[(size_t)(2 * kp + 1) * 64 + o];
        W2h[o * PW + kp] = pack_f16x2(e0, e1);
    }
    if (tid < 64) { w3s[tid] = W3[tid]; b2s[tid] = b2[tid]; }
    if (tid == 0) b3s[0] = b3[0];
    __syncthreads();

    int wid = tid >> 5, lane = tid & 31;
    int g = lane >> 2, tig = lane & 3;
    uint32_t* Xhi = Xbase + wid * 2 * 16 * PW;
    uint32_t* Xlo = Xhi + 16 * PW;
    int c0 = 4 * lane;
    const float inv_h = 1.0f / 128.0f;
    const float2* attr2 = (const float2*)attr;

    float4 w1a_r = *(const float4*)(W1 + 256 * HD + c0);
    float4 w1b_r = *(const float4*)(W1 + 257 * HD + c0);
    float4 b1_r  = *(const float4*)(b1 + c0);
    float4 g_r   = *(const float4*)(lng + c0);
    float4 be_r  = *(const float4*)(lnb + c0);
    float  b3v   = b3s[0];

    int nchunks = (E + 15) >> 4;
    int wg = blockIdx.x * 8 + wid;
    int wstride = gridDim.x * 8;

    for (int ch = wg; ch < nchunks; ch += wstride) {
        int e_base = ch << 4;

        int e_l = e_base + (lane & 15); if (e_l >= E) e_l = E - 1;
        int    i_l = eidx[e_l];
        int    j_l = eidx[(size_t)E + e_l];
        float2 a_l = attr2[e_l];

        // ---- gather + LN + ReLU + fp16 split-pack -> Xhi/Xlo (16 rows) ----
        #pragma unroll 4
        for (int ee = 0; ee < 16; ee++) {
            int   i  = __shfl_sync(0xffffffffu, i_l, ee);
            int   j  = __shfl_sync(0xffffffffu, j_l, ee);
            float ax = __shfl_sync(0xffffffffu, a_l.x, ee);
            float ay = __shfl_sync(0xffffffffu, a_l.y, ee);

            float4 pa = *(const float4*)(P + (size_t)i * PCOL + c0);
            float4 pb = *(const float4*)(P + (size_t)j * PCOL + 128 + c0);

            float h0 = pa.x + pb.x + ax * w1a_r.x + ay * w1b_r.x + b1_r.x;
            float h1 = pa.y + pb.y + ax * w1a_r.y + ay * w1b_r.y + b1_r.y;
            float h2 = pa.z + pb.z + ax * w1a_r.z + ay * w1b_r.z + b1_r.z;
            float h3 = pa.w + pb.w + ax * w1a_r.w + ay * w1b_r.w + b1_r.w;

            float s  = h0 + h1 + h2 + h3;
            float sq = h0 * h0 + h1 * h1 + h2 * h2 + h3 * h3;
            #pragma unroll
            for (int off = 16; off > 0; off >>= 1) {
                s  += __shfl_xor_sync(0xffffffffu, s,  off);
                sq += __shfl_xor_sync(0xffffffffu, sq, off);
            }
            float mean = s * inv_h;
            float var  = sq * inv_h - mean * mean;
            float rstd = rsqrtf(var + 1e-5f);

            float x0 = fmaxf((h0 - mean) * rstd * g_r.x + be_r.x, 0.f);
            float x1 = fmaxf((h1 - mean) * rstd * g_r.y + be_r.y, 0.f);
            float x2 = fmaxf((h2 - mean) * rstd * g_r.z + be_r.z, 0.f);
            float x3 = fmaxf((h3 - mean) * rstd * g_r.w + be_r.w, 0.f);

            uint32_t hA, lA, hB, lB;
            split_pair_f16(x0, x1, hA, lA);
            split_pair_f16(x2, x3, hB, lB);
            *(uint2*)(Xhi + ee * PW + 2 * lane) = make_uint2(hA, hB);
            *(uint2*)(Xlo + ee * PW + 2 * lane) = make_uint2(lA, lB);
        }
        __syncwarp();

        // ---- GEMM2: C[16][64] = (Xhi + Xlo) @ W2h + b2, 2-pass fp16 ----
        float C[8][4];
        #pragma unroll
        for (int nt = 0; nt < 8; nt++) {
            float bb0 = b2s[8 * nt + 2 * tig];
            float bb1 = b2s[8 * nt + 2 * tig + 1];
            C[nt][0] = bb0; C[nt][1] = bb1;
            C[nt][2] = bb0; C[nt][3] = bb1;
        }

        #pragma unroll
        for (int kt = 0; kt < 8; kt++) {
            int kb = kt * 8 + tig;
            uint32_t ah0 = Xhi[g       * PW + kb];
            uint32_t ah1 = Xhi[(g + 8) * PW + kb];
            uint32_t ah2 = Xhi[g       * PW + kb + 4];
            uint32_t ah3 = Xhi[(g + 8) * PW + kb + 4];
            uint32_t al0 = Xlo[g       * PW + kb];
            uint32_t al1 = Xlo[(g + 8) * PW + kb];
            uint32_t al2 = Xlo[g       * PW + kb + 4];
            uint32_t al3 = Xlo[(g + 8) * PW + kb + 4];
            #pragma unroll
            for (int nt = 0; nt < 8; nt++) {
                int nc = 8 * nt + g;
                uint32_t bh0 = W2h[nc * PW + kb], bh1 = W2h[nc * PW + kb + 4];
                mma_f16(C[nt][0], C[nt][1], C[nt][2], C[nt][3],
                        ah0, ah1, ah2, ah3, bh0, bh1);
                mma_f16(C[nt][0], C[nt][1], C[nt][2], C[nt][3],
                        al0, al1, al2, al3, bh0, bh1);
            }
        }
        __syncwarp();

        // ---- ReLU + W3 dot + reduce over tig ----
        float p0 = 0.f, p1 = 0.f;
        #pragma unroll
        for (int nt = 0; nt < 8; nt++) {
            float w30 = w3s[8 * nt + 2 * tig];
            float w31 = w3s[8 * nt + 2 * tig + 1];
            p0 += fmaxf(C[nt][0], 0.f) * w30 + fmaxf(C[nt][1], 0.f) * w31;
            p1 += fmaxf(C[nt][2], 0.f) * w30 + fmaxf(C[nt][3], 0.f) * w31;
        }
        p0 += __shfl_xor_sync(0xffffffffu, p0, 1);
        p0 += __shfl_xor_sync(0xffffffffu, p0, 2);
        p1 += __shfl_xor_sync(0xffffffffu, p1, 1);
        p1 += __shfl_xor_sync(0xffffffffu, p1, 2);

        if (tig == 0) {
            int er0 = e_base + g;
            int er1 = er0 + 8;
            if (er0 < E) out[er0] = p0 + b3v;
            if (er1 < E) out[er1] = p1 + b3v;
        }
    }
}

// ---------------------------------------------------------------------------
// Launch
// ---------------------------------------------------------------------------
extern "C" void kernel_launch(void* const* d_in, const int* in_sizes, int n_in,
                              void* d_out, int out_size)
{
    const float* node_embed = (const float*)d_in[0];
    const int*   eidx       = (const int*)d_in[1];
    const float* attr       = (const float*)d_in[2];
    const float* W1         = (const float*)d_in[3];
    const float* b1         = (const float*)d_in[4];
    const float* lng        = (const float*)d_in[5];
    const float* lnb        = (const float*)d_in[6];
    const float* W2         = (const float*)d_in[7];
    const float* b2         = (const float*)d_in[8];
    const float* W3         = (const float*)d_in[9];
    const float* b3         = (const float*)d_in[10];
    float* out = (float*)d_out;

    int N = in_sizes[0] / HD;
    int E = in_sizes[2] / 2;

    float* P = nullptr;
    cudaGetSymbolAddress((void**)&P, g_P);

    const int PRE_SMEM  = 4 * 128 * PW * 4;                              // 139264 B
    const int EDGE_SMEM = (64 * PW + 8 * 2 * 16 * PW + 129) * 4;         // 87556 B

    cudaFuncSetAttribute(precompute_kernel,
                         cudaFuncAttributeMaxDynamicSharedMemorySize, PRE_SMEM);
    cudaFuncSetAttribute(edge_kernel,
                         cudaFuncAttributeMaxDynamicSharedMemorySize, EDGE_SMEM);

    dim3 pre_grid((N + 127) / 128, 2);
    precompute_kernel<<<pre_grid, 256, PRE_SMEM>>>(node_embed, W1, P, N);

    edge_kernel<<<296, 256, EDGE_SMEM>>>(P, eidx, attr, W1, b1, lng, lnb,
                                         W2, b2, W3, b3, out, E);
}

// round 15
// speedup vs baseline: 1.3624x; 1.1677x over previous
#include <cuda_runtime.h>
#include <cuda_fp16.h>
#include <cstdint>

// ---------------------------------------------------------------------------
// EdgeScoringMLP: logit(e) = W3 . relu( relu(LN(e_in @ W1 + b1)) @ W2 + b2 ) + b3
//   e_in @ W1 = Pa[i] + Pb[j] + a0*W1[256,:] + a1*W1[257,:]   (P precomputed)
// R15: fp16-2pass Dekker (validated in R14 on the edge GEMM: rel_err 2.2e-4,
//      -13% time) now ALSO applied to the precompute GEMM:
//        P = (Ahi + Alo) @ fp16(W1)   — W1-lo array eliminated ->
//      smem 139KB -> 104KB -> 2 CTAs/SM (was 1, latency-bound), mma 24->16.
//      Edge kernel byte-identical to R14 (best measured: 236us).
// ---------------------------------------------------------------------------

#define HD 128
#define PCOL 256
#define MAXN 100000
#define PW 68              // padded row stride (u32): (4g+tig)%32 all-distinct

__device__ float g_P[(size_t)MAXN * PCOL];

// ---- fp16 helpers ---------------------------------------------------------
static __device__ __forceinline__ uint32_t pack_f16x2(float x0, float x1) {
    uint32_t d;   // lower half = x0, upper half = x1
    asm("cvt.rn.f16x2.f32 %0, %1, %2;" : "=r"(d) : "f"(x1), "f"(x0));
    return d;
}
static __device__ __forceinline__ void split_pair_f16(float x0, float x1,
                                                      uint32_t& hi, uint32_t& lo) {
    hi = pack_f16x2(x0, x1);
    __half2 h2 = *reinterpret_cast<__half2*>(&hi);
    float2 f = __half22float2(h2);
    lo = pack_f16x2(x0 - f.x, x1 - f.y);
}
static __device__ __forceinline__ void mma_f16(
    float& c0, float& c1, float& c2, float& c3,
    uint32_t a0, uint32_t a1, uint32_t a2, uint32_t a3,
    uint32_t b0, uint32_t b1)
{
    asm volatile(
        "mma.sync.aligned.m16n8k16.row.col.f32.f16.f16.f32 "
        "{%0,%1,%2,%3},{%4,%5,%6,%7},{%8,%9},{%0,%1,%2,%3};"
        : "+f"(c0), "+f"(c1), "+f"(c2), "+f"(c3)
        : "r"(a0), "r"(a1), "r"(a2), "r"(a3), "r"(b0), "r"(b1));
}

// ---------------------------------------------------------------------------
// Kernel 1: P = emb @ Wsel (fp16 2-pass).
// CTA 256 thr = 8 warps, tile 128 nodes x 128 cols (blockIdx.y = half).
// Warp (mt 0..3, nh 0..1): 32 nodes x 64 cols, two 16-row tiles share B.
// smem = Wh[128][PW] + Ahi[128][PW] + Alo[128][PW] = 104448 B -> 2 CTAs/SM.
// ---------------------------------------------------------------------------
__global__ void __launch_bounds__(256, 2)
precompute_kernel(const float* __restrict__ emb,
                  const float* __restrict__ W1,
                  float* __restrict__ P,
                  int N)
{
    extern __shared__ uint32_t smu[];
    uint32_t* Wh  = smu;                  // [128][PW]  fp16x2 packed (hi only)
    uint32_t* Ahi = Wh + 128 * PW;        // [128][PW]
    uint32_t* Alo = Ahi + 128 * PW;

    int tid  = threadIdx.x;
    int half = blockIdx.y;
    int n0g  = blockIdx.x * 128;

    for (int t = tid; t < 128 * 64; t += 256) {
        int o = t & 127, kp = t >> 7;
        float e0 = W1[(size_t)(2 * kp     + half * 128) * HD + o];
        float e1 = W1[(size_t)(2 * kp + 1 + half * 128) * HD + o];
        Wh[o * PW + kp] = pack_f16x2(e0, e1);
    }
    for (int t = tid; t < 128 * 64; t += 256) {
        int r = t >> 6, kp = t & 63;
        int node = n0g + r; if (node >= N) node = N - 1;
        float2 v = *(const float2*)(emb + (size_t)node * HD + 2 * kp);
        uint32_t hi, lo; split_pair_f16(v.x, v.y, hi, lo);
        Ahi[r * PW + kp] = hi; Alo[r * PW + kp] = lo;
    }
    __syncthreads();

    int wid = tid >> 5, lane = tid & 31;
    int g = lane >> 2, tig = lane & 3;
    int mt = wid >> 1, nh = wid & 1;
    int m0 = mt * 32;

    float C[2][8][4];
    #pragma unroll
    for (int tt = 0; tt < 2; tt++)
        #pragma unroll
        for (int nt = 0; nt < 8; nt++)
            #pragma unroll
            for (int q = 0; q < 4; q++) C[tt][nt][q] = 0.f;

    #pragma unroll
    for (int kt = 0; kt < 8; kt++) {
        int kb = kt * 8 + tig;
        uint32_t ah[2][4], al[2][4];
        #pragma unroll
        for (int tt = 0; tt < 2; tt++) {
            int r0 = m0 + tt * 16 + g;
            ah[tt][0] = Ahi[r0       * PW + kb];
            ah[tt][1] = Ahi[(r0 + 8) * PW + kb];
            ah[tt][2] = Ahi[r0       * PW + kb + 4];
            ah[tt][3] = Ahi[(r0 + 8) * PW + kb + 4];
            al[tt][0] = Alo[r0       * PW + kb];
            al[tt][1] = Alo[(r0 + 8) * PW + kb];
            al[tt][2] = Alo[r0       * PW + kb + 4];
            al[tt][3] = Alo[(r0 + 8) * PW + kb + 4];
        }
        #pragma unroll
        for (int nt = 0; nt < 8; nt++) {
            int nc = nh * 64 + nt * 8 + g;
            uint32_t bh0 = Wh[nc * PW + kb], bh1 = Wh[nc * PW + kb + 4];
            #pragma unroll
            for (int tt = 0; tt < 2; tt++) {
                mma_f16(C[tt][nt][0], C[tt][nt][1], C[tt][nt][2], C[tt][nt][3],
                        ah[tt][0], ah[tt][1], ah[tt][2], ah[tt][3], bh0, bh1);
                mma_f16(C[tt][nt][0], C[tt][nt][1], C[tt][nt][2], C[tt][nt][3],
                        al[tt][0], al[tt][1], al[tt][2], al[tt][3], bh0, bh1);
            }
        }
    }

    #pragma unroll
    for (int tt = 0; tt < 2; tt++) {
        int r0 = n0g + m0 + tt * 16 + g;
        int r1 = r0 + 8;
        #pragma unroll
        for (int nt = 0; nt < 8; nt++) {
            int col = half * 128 + nh * 64 + nt * 8 + 2 * tig;
            if (r0 < N) *(float2*)(P + (size_t)r0 * PCOL + col) =
                make_float2(C[tt][nt][0], C[tt][nt][1]);
            if (r1 < N) *(float2*)(P + (size_t)r1 * PCOL + col) =
                make_float2(C[tt][nt][2], C[tt][nt][3]);
        }
    }
}

// ---------------------------------------------------------------------------
// Kernel 2: persistent fused edge pipeline (R14 verbatim — best measured).
// 16 edges per warp-chunk, 2 CTAs/SM, LN consts in regs, lane prefetch,
// fp16 2-pass GEMM2: D = (Xhi + Xlo) @ fp16(W2).
// ---------------------------------------------------------------------------
__global__ void __launch_bounds__(256, 2)
edge_kernel(const float* __restrict__ P,
            const int* __restrict__ eidx,        // [2][E] int32
            const float* __restrict__ attr,      // [E][2]
            const float* __restrict__ W1,        // rows 256,257
            const float* __restrict__ b1,
            const float* __restrict__ lng,
            const float* __restrict__ lnb,
            const float* __restrict__ W2,        // [128][64]
            const float* __restrict__ b2,
            const float* __restrict__ W3,
            const float* __restrict__ b3,
            float* __restrict__ out,
            int E)
{
    extern __shared__ uint32_t smu[];
    uint32_t* W2h  = smu;                      // [64][PW]   fp16x2 packed
    uint32_t* Xbase = W2h + 64 * PW;           // 8 warps x (Xhi[16][PW], Xlo[16][PW])
    float* w3s = (float*)(Xbase + 8 * 2 * 16 * PW);   // 64
    float* b2s = w3s + 64;                             // 64
    float* b3s = b2s + 64;                             // 1

    int tid = threadIdx.x;

    for (int t = tid; t < 64 * 64; t += 256) {
        int kp = t >> 6, o = t & 63;
        float e0 = W2[(size_t)(2 * kp)     * 64 + o];
        float e1 = W2[(size_t)(2 * kp + 1) * 64 + o];
        W2h[o * PW + kp] = pack_f16x2(e0, e1);
    }
    if (tid < 64) { w3s[tid] = W3[tid]; b2s[tid] = b2[tid]; }
    if (tid == 0) b3s[0] = b3[0];
    __syncthreads();

    int wid = tid >> 5, lane = tid & 31;
    int g = lane >> 2, tig = lane & 3;
    uint32_t* Xhi = Xbase + wid * 2 * 16 * PW;
    uint32_t* Xlo = Xhi + 16 * PW;
    int c0 = 4 * lane;
    const float inv_h = 1.0f / 128.0f;
    const float2* attr2 = (const float2*)attr;

    float4 w1a_r = *(const float4*)(W1 + 256 * HD + c0);
    float4 w1b_r = *(const float4*)(W1 + 257 * HD + c0);
    float4 b1_r  = *(const float4*)(b1 + c0);
    float4 g_r   = *(const float4*)(lng + c0);
    float4 be_r  = *(const float4*)(lnb + c0);
    float  b3v   = b3s[0];

    int nchunks = (E + 15) >> 4;
    int wg = blockIdx.x * 8 + wid;
    int wstride = gridDim.x * 8;

    for (int ch = wg; ch < nchunks; ch += wstride) {
        int e_base = ch << 4;

        int e_l = e_base + (lane & 15); if (e_l >= E) e_l = E - 1;
        int    i_l = eidx[e_l];
        int    j_l = eidx[(size_t)E + e_l];
        float2 a_l = attr2[e_l];

        // ---- gather + LN + ReLU + fp16 split-pack -> Xhi/Xlo (16 rows) ----
        #pragma unroll 4
        for (int ee = 0; ee < 16; ee++) {
            int   i  = __shfl_sync(0xffffffffu, i_l, ee);
            int   j  = __shfl_sync(0xffffffffu, j_l, ee);
            float ax = __shfl_sync(0xffffffffu, a_l.x, ee);
            float ay = __shfl_sync(0xffffffffu, a_l.y, ee);

            float4 pa = *(const float4*)(P + (size_t)i * PCOL + c0);
            float4 pb = *(const float4*)(P + (size_t)j * PCOL + 128 + c0);

            float h0 = pa.x + pb.x + ax * w1a_r.x + ay * w1b_r.x + b1_r.x;
            float h1 = pa.y + pb.y + ax * w1a_r.y + ay * w1b_r.y + b1_r.y;
            float h2 = pa.z + pb.z + ax * w1a_r.z + ay * w1b_r.z + b1_r.z;
            float h3 = pa.w + pb.w + ax * w1a_r.w + ay * w1b_r.w + b1_r.w;

            float s  = h0 + h1 + h2 + h3;
            float sq = h0 * h0 + h1 * h1 + h2 * h2 + h3 * h3;
            #pragma unroll
            for (int off = 16; off > 0; off >>= 1) {
                s  += __shfl_xor_sync(0xffffffffu, s,  off);
                sq += __shfl_xor_sync(0xffffffffu, sq, off);
            }
            float mean = s * inv_h;
            float var  = sq * inv_h - mean * mean;
            float rstd = rsqrtf(var + 1e-5f);

            float x0 = fmaxf((h0 - mean) * rstd * g_r.x + be_r.x, 0.f);
            float x1 = fmaxf((h1 - mean) * rstd * g_r.y + be_r.y, 0.f);
            float x2 = fmaxf((h2 - mean) * rstd * g_r.z + be_r.z, 0.f);
            float x3 = fmaxf((h3 - mean) * rstd * g_r.w + be_r.w, 0.f);

            uint32_t hA, lA, hB, lB;
            split_pair_f16(x0, x1, hA, lA);
            split_pair_f16(x2, x3, hB, lB);
            *(uint2*)(Xhi + ee * PW + 2 * lane) = make_uint2(hA, hB);
            *(uint2*)(Xlo + ee * PW + 2 * lane) = make_uint2(lA, lB);
        }
        __syncwarp();

        // ---- GEMM2: C[16][64] = (Xhi + Xlo) @ W2h + b2, 2-pass fp16 ----
        float C[8][4];
        #pragma unroll
        for (int nt = 0; nt < 8; nt++) {
            float bb0 = b2s[8 * nt + 2 * tig];
            float bb1 = b2s[8 * nt + 2 * tig + 1];
            C[nt][0] = bb0; C[nt][1] = bb1;
            C[nt][2] = bb0; C[nt][3] = bb1;
        }

        #pragma unroll
        for (int kt = 0; kt < 8; kt++) {
            int kb = kt * 8 + tig;
            uint32_t ah0 = Xhi[g       * PW + kb];
            uint32_t ah1 = Xhi[(g + 8) * PW + kb];
            uint32_t ah2 = Xhi[g       * PW + kb + 4];
            uint32_t ah3 = Xhi[(g + 8) * PW + kb + 4];
            uint32_t al0 = Xlo[g       * PW + kb];
            uint32_t al1 = Xlo[(g + 8) * PW + kb];
            uint32_t al2 = Xlo[g       * PW + kb + 4];
            uint32_t al3 = Xlo[(g + 8) * PW + kb + 4];
            #pragma unroll
            for (int nt = 0; nt < 8; nt++) {
                int nc = 8 * nt + g;
                uint32_t bh0 = W2h[nc * PW + kb], bh1 = W2h[nc * PW + kb + 4];
                mma_f16(C[nt][0], C[nt][1], C[nt][2], C[nt][3],
                        ah0, ah1, ah2, ah3, bh0, bh1);
                mma_f16(C[nt][0], C[nt][1], C[nt][2], C[nt][3],
                        al0, al1, al2, al3, bh0, bh1);
            }
        }
        __syncwarp();

        // ---- ReLU + W3 dot + reduce over tig ----
        float p0 = 0.f, p1 = 0.f;
        #pragma unroll
        for (int nt = 0; nt < 8; nt++) {
            float w30 = w3s[8 * nt + 2 * tig];
            float w31 = w3s[8 * nt + 2 * tig + 1];
            p0 += fmaxf(C[nt][0], 0.f) * w30 + fmaxf(C[nt][1], 0.f) * w31;
            p1 += fmaxf(C[nt][2], 0.f) * w30 + fmaxf(C[nt][3], 0.f) * w31;
        }
        p0 += __shfl_xor_sync(0xffffffffu, p0, 1);
        p0 += __shfl_xor_sync(0xffffffffu, p0, 2);
        p1 += __shfl_xor_sync(0xffffffffu, p1, 1);
        p1 += __shfl_xor_sync(0xffffffffu, p1, 2);

        if (tig == 0) {
            int er0 = e_base + g;
            int er1 = er0 + 8;
            if (er0 < E) out[er0] = p0 + b3v;
            if (er1 < E) out[er1] = p1 + b3v;
        }
    }
}

// ---------------------------------------------------------------------------
// Launch
// ---------------------------------------------------------------------------
extern "C" void kernel_launch(void* const* d_in, const int* in_sizes, int n_in,
                              void* d_out, int out_size)
{
    const float* node_embed = (const float*)d_in[0];
    const int*   eidx       = (const int*)d_in[1];
    const float* attr       = (const float*)d_in[2];
    const float* W1         = (const float*)d_in[3];
    const float* b1         = (const float*)d_in[4];
    const float* lng        = (const float*)d_in[5];
    const float* lnb        = (const float*)d_in[6];
    const float* W2         = (const float*)d_in[7];
    const float* b2         = (const float*)d_in[8];
    const float* W3         = (const float*)d_in[9];
    const float* b3         = (const float*)d_in[10];
    float* out = (float*)d_out;

    int N = in_sizes[0] / HD;
    int E = in_sizes[2] / 2;

    float* P = nullptr;
    cudaGetSymbolAddress((void**)&P, g_P);

    const int PRE_SMEM  = 3 * 128 * PW * 4;                              // 104448 B
    const int EDGE_SMEM = (64 * PW + 8 * 2 * 16 * PW + 129) * 4;         // 87556 B

    cudaFuncSetAttribute(precompute_kernel,
                         cudaFuncAttributeMaxDynamicSharedMemorySize, PRE_SMEM);
    cudaFuncSetAttribute(edge_kernel,
                         cudaFuncAttributeMaxDynamicSharedMemorySize, EDGE_SMEM);

    dim3 pre_grid((N + 127) / 128, 2);
    precompute_kernel<<<pre_grid, 256, PRE_SMEM>>>(node_embed, W1, P, N);

    edge_kernel<<<296, 256, EDGE_SMEM>>>(P, eidx, attr, W1, b1, lng, lnb,
                                         W2, b2, W3, b3, out, E);
}

// round 17
// speedup vs baseline: 1.5402x; 1.1305x over previous
#include <cuda_runtime.h>
#include <cuda_fp16.h>
#include <cstdint>

// ---------------------------------------------------------------------------
// EdgeScoringMLP: logit(e) = W3 . relu( relu(LN(e_in @ W1 + b1)) @ W2 + b2 ) + b3
//   e_in @ W1 = Pa[i] + Pb[j] + a0*W1[256,:] + a1*W1[257,:]   (P precomputed)
// R17 (= R16 resubmit after broker infra failure): edge GEMM2 X operand is
//      SINGLE-pass fp16 (Xlo deleted): D = fp16(X) @ fp16(W2).
//      mma count halves, X smem/store/load traffic halves. Calibrated error
//      model predicts rel_err ~4-5.5e-4 (gate 1e-3). Precompute = R15
//      (fp16 A-2pass/W-1pass, 2 CTAs/SM, measured ~78us).
// ---------------------------------------------------------------------------

#define HD 128
#define PCOL 256
#define MAXN 100000
#define PW 68              // padded row stride (u32): (4g+tig)%32 all-distinct

__device__ float g_P[(size_t)MAXN * PCOL];

// ---- fp16 helpers ---------------------------------------------------------
static __device__ __forceinline__ uint32_t pack_f16x2(float x0, float x1) {
    uint32_t d;   // lower half = x0, upper half = x1
    asm("cvt.rn.f16x2.f32 %0, %1, %2;" : "=r"(d) : "f"(x1), "f"(x0));
    return d;
}
static __device__ __forceinline__ void split_pair_f16(float x0, float x1,
                                                      uint32_t& hi, uint32_t& lo) {
    hi = pack_f16x2(x0, x1);
    __half2 h2 = *reinterpret_cast<__half2*>(&hi);
    float2 f = __half22float2(h2);
    lo = pack_f16x2(x0 - f.x, x1 - f.y);
}
static __device__ __forceinline__ void mma_f16(
    float& c0, float& c1, float& c2, float& c3,
    uint32_t a0, uint32_t a1, uint32_t a2, uint32_t a3,
    uint32_t b0, uint32_t b1)
{
    asm volatile(
        "mma.sync.aligned.m16n8k16.row.col.f32.f16.f16.f32 "
        "{%0,%1,%2,%3},{%4,%5,%6,%7},{%8,%9},{%0,%1,%2,%3};"
        : "+f"(c0), "+f"(c1), "+f"(c2), "+f"(c3)
        : "r"(a0), "r"(a1), "r"(a2), "r"(a3), "r"(b0), "r"(b1));
}

// ---------------------------------------------------------------------------
// Kernel 1: P = emb @ Wsel (fp16: A 2-pass, W 1-pass).  (R15 — measured 78us)
// CTA 256 thr = 8 warps, tile 128 nodes x 128 cols (blockIdx.y = half).
// ---------------------------------------------------------------------------
__global__ void __launch_bounds__(256, 2)
precompute_kernel(const float* __restrict__ emb,
                  const float* __restrict__ W1,
                  float* __restrict__ P,
                  int N)
{
    extern __shared__ uint32_t smu[];
    uint32_t* Wh  = smu;                  // [128][PW]  fp16x2 packed
    uint32_t* Ahi = Wh + 128 * PW;        // [128][PW]
    uint32_t* Alo = Ahi + 128 * PW;

    int tid  = threadIdx.x;
    int half = blockIdx.y;
    int n0g  = blockIdx.x * 128;

    for (int t = tid; t < 128 * 64; t += 256) {
        int o = t & 127, kp = t >> 7;
        float e0 = W1[(size_t)(2 * kp     + half * 128) * HD + o];
        float e1 = W1[(size_t)(2 * kp + 1 + half * 128) * HD + o];
        Wh[o * PW + kp] = pack_f16x2(e0, e1);
    }
    for (int t = tid; t < 128 * 64; t += 256) {
        int r = t >> 6, kp = t & 63;
        int node = n0g + r; if (node >= N) node = N - 1;
        float2 v = *(const float2*)(emb + (size_t)node * HD + 2 * kp);
        uint32_t hi, lo; split_pair_f16(v.x, v.y, hi, lo);
        Ahi[r * PW + kp] = hi; Alo[r * PW + kp] = lo;
    }
    __syncthreads();

    int wid = tid >> 5, lane = tid & 31;
    int g = lane >> 2, tig = lane & 3;
    int mt = wid >> 1, nh = wid & 1;
    int m0 = mt * 32;

    float C[2][8][4];
    #pragma unroll
    for (int tt = 0; tt < 2; tt++)
        #pragma unroll
        for (int nt = 0; nt < 8; nt++)
            #pragma unroll
            for (int q = 0; q < 4; q++) C[tt][nt][q] = 0.f;

    #pragma unroll
    for (int kt = 0; kt < 8; kt++) {
        int kb = kt * 8 + tig;
        uint32_t ah[2][4], al[2][4];
        #pragma unroll
        for (int tt = 0; tt < 2; tt++) {
            int r0 = m0 + tt * 16 + g;
            ah[tt][0] = Ahi[r0       * PW + kb];
            ah[tt][1] = Ahi[(r0 + 8) * PW + kb];
            ah[tt][2] = Ahi[r0       * PW + kb + 4];
            ah[tt][3] = Ahi[(r0 + 8) * PW + kb + 4];
            al[tt][0] = Alo[r0       * PW + kb];
            al[tt][1] = Alo[(r0 + 8) * PW + kb];
            al[tt][2] = Alo[r0       * PW + kb + 4];
            al[tt][3] = Alo[(r0 + 8) * PW + kb + 4];
        }
        #pragma unroll
        for (int nt = 0; nt < 8; nt++) {
            int nc = nh * 64 + nt * 8 + g;
            uint32_t bh0 = Wh[nc * PW + kb], bh1 = Wh[nc * PW + kb + 4];
            #pragma unroll
            for (int tt = 0; tt < 2; tt++) {
                mma_f16(C[tt][nt][0], C[tt][nt][1], C[tt][nt][2], C[tt][nt][3],
                        ah[tt][0], ah[tt][1], ah[tt][2], ah[tt][3], bh0, bh1);
                mma_f16(C[tt][nt][0], C[tt][nt][1], C[tt][nt][2], C[tt][nt][3],
                        al[tt][0], al[tt][1], al[tt][2], al[tt][3], bh0, bh1);
            }
        }
    }

    #pragma unroll
    for (int tt = 0; tt < 2; tt++) {
        int r0 = n0g + m0 + tt * 16 + g;
        int r1 = r0 + 8;
        #pragma unroll
        for (int nt = 0; nt < 8; nt++) {
            int col = half * 128 + nh * 64 + nt * 8 + 2 * tig;
            if (r0 < N) *(float2*)(P + (size_t)r0 * PCOL + col) =
                make_float2(C[tt][nt][0], C[tt][nt][1]);
            if (r1 < N) *(float2*)(P + (size_t)r1 * PCOL + col) =
                make_float2(C[tt][nt][2], C[tt][nt][3]);
        }
    }
}

// ---------------------------------------------------------------------------
// Kernel 2: persistent fused edge pipeline (R14 structure, X single-pass).
// 16 edges per warp-chunk, 2 CTAs/SM, LN consts in regs, lane prefetch.
// GEMM2: D = fp16(X) @ fp16(W2) — one mma pass.
// ---------------------------------------------------------------------------
__global__ void __launch_bounds__(256, 2)
edge_kernel(const float* __restrict__ P,
            const int* __restrict__ eidx,        // [2][E] int32
            const float* __restrict__ attr,      // [E][2]
            const float* __restrict__ W1,        // rows 256,257
            const float* __restrict__ b1,
            const float* __restrict__ lng,
            const float* __restrict__ lnb,
            const float* __restrict__ W2,        // [128][64]
            const float* __restrict__ b2,
            const float* __restrict__ W3,
            const float* __restrict__ b3,
            float* __restrict__ out,
            int E)
{
    extern __shared__ uint32_t smu[];
    uint32_t* W2h  = smu;                      // [64][PW]   fp16x2 packed
    uint32_t* Xbase = W2h + 64 * PW;           // 8 warps x X[16][PW]
    float* w3s = (float*)(Xbase + 8 * 16 * PW);       // 64
    float* b2s = w3s + 64;                             // 64
    float* b3s = b2s + 64;                             // 1

    int tid = threadIdx.x;

    for (int t = tid; t < 64 * 64; t += 256) {
        int kp = t >> 6, o = t & 63;
        float e0 = W2[(size_t)(2 * kp)     * 64 + o];
        float e1 = W2[(size_t)(2 * kp + 1) * 64 + o];
        W2h[o * PW + kp] = pack_f16x2(e0, e1);
    }
    if (tid < 64) { w3s[tid] = W3[tid]; b2s[tid] = b2[tid]; }
    if (tid == 0) b3s[0] = b3[0];
    __syncthreads();

    int wid = tid >> 5, lane = tid & 31;
    int g = lane >> 2, tig = lane & 3;
    uint32_t* Xw = Xbase + wid * 16 * PW;
    int c0 = 4 * lane;
    const float inv_h = 1.0f / 128.0f;
    const float2* attr2 = (const float2*)attr;

    float4 w1a_r = *(const float4*)(W1 + 256 * HD + c0);
    float4 w1b_r = *(const float4*)(W1 + 257 * HD + c0);
    float4 b1_r  = *(const float4*)(b1 + c0);
    float4 g_r   = *(const float4*)(lng + c0);
    float4 be_r  = *(const float4*)(lnb + c0);
    float  b3v   = b3s[0];

    int nchunks = (E + 15) >> 4;
    int wg = blockIdx.x * 8 + wid;
    int wstride = gridDim.x * 8;

    for (int ch = wg; ch < nchunks; ch += wstride) {
        int e_base = ch << 4;

        int e_l = e_base + (lane & 15); if (e_l >= E) e_l = E - 1;
        int    i_l = eidx[e_l];
        int    j_l = eidx[(size_t)E + e_l];
        float2 a_l = attr2[e_l];

        // ---- gather + LN + ReLU + fp16 pack -> X (16 rows) ----
        #pragma unroll 4
        for (int ee = 0; ee < 16; ee++) {
            int   i  = __shfl_sync(0xffffffffu, i_l, ee);
            int   j  = __shfl_sync(0xffffffffu, j_l, ee);
            float ax = __shfl_sync(0xffffffffu, a_l.x, ee);
            float ay = __shfl_sync(0xffffffffu, a_l.y, ee);

            float4 pa = *(const float4*)(P + (size_t)i * PCOL + c0);
            float4 pb = *(const float4*)(P + (size_t)j * PCOL + 128 + c0);

            float h0 = pa.x + pb.x + ax * w1a_r.x + ay * w1b_r.x + b1_r.x;
            float h1 = pa.y + pb.y + ax * w1a_r.y + ay * w1b_r.y + b1_r.y;
            float h2 = pa.z + pb.z + ax * w1a_r.z + ay * w1b_r.z + b1_r.z;
            float h3 = pa.w + pb.w + ax * w1a_r.w + ay * w1b_r.w + b1_r.w;

            float s  = h0 + h1 + h2 + h3;
            float sq = h0 * h0 + h1 * h1 + h2 * h2 + h3 * h3;
            #pragma unroll
            for (int off = 16; off > 0; off >>= 1) {
                s  += __shfl_xor_sync(0xffffffffu, s,  off);
                sq += __shfl_xor_sync(0xffffffffu, sq, off);
            }
            float mean = s * inv_h;
            float var  = sq * inv_h - mean * mean;
            float rstd = rsqrtf(var + 1e-5f);

            float x0 = fmaxf((h0 - mean) * rstd * g_r.x + be_r.x, 0.f);
            float x1 = fmaxf((h1 - mean) * rstd * g_r.y + be_r.y, 0.f);
            float x2 = fmaxf((h2 - mean) * rstd * g_r.z + be_r.z, 0.f);
            float x3 = fmaxf((h3 - mean) * rstd * g_r.w + be_r.w, 0.f);

            uint32_t hA = pack_f16x2(x0, x1);
            uint32_t hB = pack_f16x2(x2, x3);
            *(uint2*)(Xw + ee * PW + 2 * lane) = make_uint2(hA, hB);
        }
        __syncwarp();

        // ---- GEMM2: C[16][64] = X @ W2h + b2, single fp16 pass ----
        float C[8][4];
        #pragma unroll
        for (int nt = 0; nt < 8; nt++) {
            float bb0 = b2s[8 * nt + 2 * tig];
            float bb1 = b2s[8 * nt + 2 * tig + 1];
            C[nt][0] = bb0; C[nt][1] = bb1;
            C[nt][2] = bb0; C[nt][3] = bb1;
        }

        #pragma unroll
        for (int kt = 0; kt < 8; kt++) {
            int kb = kt * 8 + tig;
            uint32_t ah0 = Xw[g       * PW + kb];
            uint32_t ah1 = Xw[(g + 8) * PW + kb];
            uint32_t ah2 = Xw[g       * PW + kb + 4];
            uint32_t ah3 = Xw[(g + 8) * PW + kb + 4];
            #pragma unroll
            for (int nt = 0; nt < 8; nt++) {
                int nc = 8 * nt + g;
                uint32_t bh0 = W2h[nc * PW + kb], bh1 = W2h[nc * PW + kb + 4];
                mma_f16(C[nt][0], C[nt][1], C[nt][2], C[nt][3],
                        ah0, ah1, ah2, ah3, bh0, bh1);
            }
        }
        __syncwarp();

        // ---- ReLU + W3 dot + reduce over tig ----
        float p0 = 0.f, p1 = 0.f;
        #pragma unroll
        for (int nt = 0; nt < 8; nt++) {
            float w30 = w3s[8 * nt + 2 * tig];
            float w31 = w3s[8 * nt + 2 * tig + 1];
            p0 += fmaxf(C[nt][0], 0.f) * w30 + fmaxf(C[nt][1], 0.f) * w31;
            p1 += fmaxf(C[nt][2], 0.f) * w30 + fmaxf(C[nt][3], 0.f) * w31;
        }
        p0 += __shfl_xor_sync(0xffffffffu, p0, 1);
        p0 += __shfl_xor_sync(0xffffffffu, p0, 2);
        p1 += __shfl_xor_sync(0xffffffffu, p1, 1);
        p1 += __shfl_xor_sync(0xffffffffu, p1, 2);

        if (tig == 0) {
            int er0 = e_base + g;
            int er1 = er0 + 8;
            if (er0 < E) out[er0] = p0 + b3v;
            if (er1 < E) out[er1] = p1 + b3v;
        }
    }
}

// ---------------------------------------------------------------------------
// Launch
// ---------------------------------------------------------------------------
extern "C" void kernel_launch(void* const* d_in, const int* in_sizes, int n_in,
                              void* d_out, int out_size)
{
    const float* node_embed = (const float*)d_in[0];
    const int*   eidx       = (const int*)d_in[1];
    const float* attr       = (const float*)d_in[2];
    const float* W1         = (const float*)d_in[3];
    const float* b1         = (const float*)d_in[4];
    const float* lng        = (const float*)d_in[5];
    const float* lnb        = (const float*)d_in[6];
    const float* W2         = (const float*)d_in[7];
    const float* b2         = (const float*)d_in[8];
    const float* W3         = (const float*)d_in[9];
    const float* b3         = (const float*)d_in[10];
    float* out = (float*)d_out;

    int N = in_sizes[0] / HD;
    int E = in_sizes[2] / 2;

    float* P = nullptr;
    cudaGetSymbolAddress((void**)&P, g_P);

    const int PRE_SMEM  = 3 * 128 * PW * 4;                          // 104448 B
    const int EDGE_SMEM = (64 * PW + 8 * 16 * PW + 129) * 4;         // 52740 B

    cudaFuncSetAttribute(precompute_kernel,
                         cudaFuncAttributeMaxDynamicSharedMemorySize, PRE_SMEM);
    cudaFuncSetAttribute(edge_kernel,
                         cudaFuncAttributeMaxDynamicSharedMemorySize, EDGE_SMEM);

    dim3 pre_grid((N + 127) / 128, 2);
    precompute_kernel<<<pre_grid, 256, PRE_SMEM>>>(node_embed, W1, P, N);

    edge_kernel<<<296, 256, EDGE_SMEM>>>(P, eidx, attr, W1, b1, lng, lnb,
                                         W2, b2, W3, b3, out, E);
}